// round 15
// baseline (speedup 1.0000x reference)
#include <cuda_runtime.h>
#include <math.h>
#include <stdint.h>

#define Bsz 4
#define AT 128
#define NBR 20
#define NK 19
#define R2 (Bsz*AT*NBR)        // 10240 edge rows
#define NODES (Bsz*AT)         // 512
#define CNT3 (R2*NK)           // 194560 three-body rows
#define OFF3 (256*256)         // BN3 partial offset in d_psum/d_psq
#define GEMM_SMEM (3*64*68*4 + 64*12 + 512*4)   // 55040 bytes

// ---------------- scratch (static device globals; no allocation) ----------------
__device__ float d_Y2[R2*256];        // two-body pre-BN GEMM output
__device__ float d_PN[NODES*768];     // node @ [W3a|W3b|W3c]
__device__ float d_QE[R2*512];        // edge @ [W3d|W3e]
__device__ float d_TB[R2*128];        // three-body pre-final-BN sums
__device__ float d_Wg[R2*128];        // per-edge w gate part
__device__ float d_We[R2*128];        // per-edge w ext part
__device__ float d_S[NODES*256];      // per-node sum of w over its 20 neighbors
__device__ float d_Q[NODES*256];      // per-node sum of w^2
__device__ float d_WhB[768*256];      // pre-split tf32 hi of [W3(640x256); W2(128x256)]
__device__ float d_WlB[768*256];      // pre-split tf32 lo
__device__ float d_psum[OFF3 + 640*256];
__device__ float d_psq [OFF3 + 640*256];
__device__ float d_pSs[1280*128];     // final-BN partials (from pass2 epilogue)
__device__ float d_pSq[1280*128];
__device__ float d_scale2[256], d_shift2[256];
__device__ float d_scale3[256], d_shift3[256];
__device__ float d_scaleS[128], d_shiftS[128];

__device__ __forceinline__ float tanh_hw(float x) {
    float y; asm("tanh.approx.f32 %0, %1;" : "=f"(y) : "f"(x)); return y;
}
__device__ __forceinline__ float sigmoid_hw(float x) {
    return fmaf(tanh_hw(0.5f*x), 0.5f, 0.5f);
}

// ---------------- tf32 helpers ----------------
__device__ __forceinline__ uint32_t f2tf32(float x) {
    uint32_t r; asm("cvt.rna.tf32.f32 %0, %1;" : "=r"(r) : "f"(x)); return r;
}
__device__ __forceinline__ void split_tf32(float x, uint32_t& hi, uint32_t& lo) {
    uint32_t h = f2tf32(x);
    hi = h;
    lo = f2tf32(x - __uint_as_float(h));
}
__device__ __forceinline__ void mma_tf32(float* d, const uint32_t* a, const uint32_t* b) {
    asm("mma.sync.aligned.m16n8k8.row.col.f32.tf32.tf32.f32 "
        "{%0,%1,%2,%3}, {%4,%5,%6,%7}, {%8,%9}, {%0,%1,%2,%3};"
        : "+f"(d[0]), "+f"(d[1]), "+f"(d[2]), "+f"(d[3])
        : "r"(a[0]), "r"(a[1]), "r"(a[2]), "r"(a[3]), "r"(b[0]), "r"(b[1]));
}

// ---------------- weight pre-split: [W3; W2] -> tf32 hi/lo ----------------
__global__ void k_split(const float* __restrict__ W3, const float* __restrict__ W2) {
    int idx = blockIdx.x*256 + threadIdx.x;     // 768*256 elements, grid 768
    float v = (idx < 640*256) ? W3[idx] : W2[idx - 640*256];
    uint32_t h, l;
    split_tf32(v, h, l);
    d_WhB[idx] = __uint_as_float(h);
    d_WlB[idx] = __uint_as_float(l);
}

// ---------------- one fused GEMM launch for PN, QE, Y2 (3xTF32, pre-split B) ----------------
// grid (12, 168): yt<160,xt<8: QE | yt<160,xt>=8: Y2 (c2 fused) | yt>=160: PN
// 8 warps = 4(M) x 2(N); warp tile 16x32 via mma.m16n8k8. A split in-loop; B pre-split (global).
__global__ void __launch_bounds__(256) gemm_all(
    const float* __restrict__ node, const float* __restrict__ edge,
    const int* __restrict__ nbr_idx, const int* __restrict__ nbr_mask) {
    extern __shared__ float smem[];
    float (*Ast)[68] = (float(*)[68])smem;                 // [64][68]
    float (*Bh)[68]  = (float(*)[68])(smem + 64*68);       // [64][68]
    float (*Bl)[68]  = (float(*)[68])(smem + 2*64*68);     // [64][68]
    float* tail = smem + 3*64*68;
    int*   sRI = (int*)tail;
    int*   sRJ = sRI + 64;
    float* sM  = (float*)(sRJ + 64);
    float* stS = sM + 64;          // [4][64]
    float* stQ = stS + 256;        // [4][64]

    int tid = threadIdx.x;
    int w = tid >> 5, lane = tid & 31;
    int wm = w >> 1, wn = w & 1;
    int gid = lane >> 2, tig = lane & 3;
    int xt = blockIdx.x, yt = blockIdx.y;

    const float* A; float* C;
    int ldc, cbase, m0, n0, mode, brow;
    if (yt >= 160) {                       // PN
        mode = 2; m0 = (yt - 160)*64; n0 = xt*64;
        A = node; brow = (n0 >> 8)*128; cbase = n0 & 255;
        C = d_PN; ldc = 768;
    } else if (xt < 8) {                   // QE
        mode = 0; m0 = yt*64; n0 = xt*64;
        A = edge; brow = (3 + (n0 >> 8))*128; cbase = n0 & 255;
        C = d_QE; ldc = 512;
    } else {                               // Y2 (c2 fused)
        mode = 1; m0 = yt*64; n0 = (xt - 8)*64;
        A = node; brow = 640; cbase = n0;
        C = d_Y2; ldc = 256;
        if (tid < 64) {
            int r = m0 + tid;
            int j = nbr_idx[r];
            int b = r / (AT*NBR);
            sRI[tid] = (r / NBR)*128;
            sRJ[tid] = (b*AT + j)*128;
            sM[tid]  = (float)nbr_mask[r];
        }
        __syncthreads();
    }

    float acc[4][4] = {};   // [n-frag][c0..c3]
    for (int k0 = 0; k0 < 128; k0 += 64) {
        if (mode == 1) {
            #pragma unroll
            for (int l = 0; l < 4; l++) {
                int f = l*256 + tid;
                int m = f >> 4, k4 = (f & 15)*4;
                float4 vi = *(const float4*)&node[sRI[m] + k0 + k4];
                float4 vj = *(const float4*)&node[sRJ[m] + k0 + k4];
                float mm = sM[m];
                Ast[k4+0][m] = vi.x*vj.x*mm;
                Ast[k4+1][m] = vi.y*vj.y*mm;
                Ast[k4+2][m] = vi.z*vj.z*mm;
                Ast[k4+3][m] = vi.w*vj.w*mm;
            }
        } else {
            #pragma unroll
            for (int l = 0; l < 4; l++) {
                int f = l*256 + tid;
                int m = f >> 4, k4 = (f & 15)*4;
                float4 v = *(const float4*)&A[(m0 + m)*128 + k0 + k4];
                Ast[k4+0][m] = v.x;
                Ast[k4+1][m] = v.y;
                Ast[k4+2][m] = v.z;
                Ast[k4+3][m] = v.w;
            }
        }
        #pragma unroll
        for (int l = 0; l < 4; l++) {
            int f = l*256 + tid;
            int k = f >> 4, n4 = (f & 15)*4;
            int gidx = (brow + k0 + k)*256 + cbase + n4;
            *(float4*)&Bh[k][n4] = *(const float4*)&d_WhB[gidx];
            *(float4*)&Bl[k][n4] = *(const float4*)&d_WlB[gidx];
        }
        __syncthreads();

        int mA = wm*16 + gid;
        #pragma unroll
        for (int k8 = 0; k8 < 64; k8 += 8) {
            uint32_t ah[4], al[4];
            split_tf32(Ast[k8+tig  ][mA  ], ah[0], al[0]);
            split_tf32(Ast[k8+tig  ][mA+8], ah[1], al[1]);
            split_tf32(Ast[k8+tig+4][mA  ], ah[2], al[2]);
            split_tf32(Ast[k8+tig+4][mA+8], ah[3], al[3]);
            #pragma unroll
            for (int f = 0; f < 4; f++) {
                int nB = wn*32 + f*8 + gid;
                uint32_t bh[2], bl[2];
                bh[0] = __float_as_uint(Bh[k8+tig  ][nB]);
                bh[1] = __float_as_uint(Bh[k8+tig+4][nB]);
                bl[0] = __float_as_uint(Bl[k8+tig  ][nB]);
                bl[1] = __float_as_uint(Bl[k8+tig+4][nB]);
                mma_tf32(acc[f], ah, bh);
                mma_tf32(acc[f], ah, bl);
                mma_tf32(acc[f], al, bh);
            }
        }
        __syncthreads();
    }

    // epilogue: scattered float2 stores (cols 2*tig, 2*tig+1 contiguous)
    {
        int mrow = m0 + wm*16 + gid;
        #pragma unroll
        for (int f = 0; f < 4; f++) {
            int ncol = n0 + wn*32 + f*8 + 2*tig;
            *(float2*)&C[ mrow   *ldc + ncol] = make_float2(acc[f][0], acc[f][1]);
            *(float2*)&C[(mrow+8)*ldc + ncol] = make_float2(acc[f][2], acc[f][3]);
        }
    }

    // fused BN2 tile stats (Y2 tiles only)
    if (mode == 1) {
        #pragma unroll
        for (int f = 0; f < 4; f++) {
            float s0 = acc[f][0] + acc[f][2];
            float s1 = acc[f][1] + acc[f][3];
            float q0 = acc[f][0]*acc[f][0] + acc[f][2]*acc[f][2];
            float q1 = acc[f][1]*acc[f][1] + acc[f][3]*acc[f][3];
            #pragma unroll
            for (int off = 4; off < 32; off <<= 1) {
                s0 += __shfl_xor_sync(0xffffffffu, s0, off);
                s1 += __shfl_xor_sync(0xffffffffu, s1, off);
                q0 += __shfl_xor_sync(0xffffffffu, q0, off);
                q1 += __shfl_xor_sync(0xffffffffu, q1, off);
            }
            if (gid == 0) {
                int nc = wn*32 + f*8 + 2*tig;
                stS[wm*64 + nc] = s0; stS[wm*64 + nc+1] = s1;
                stQ[wm*64 + nc] = q0; stQ[wm*64 + nc+1] = q1;
            }
        }
        __syncthreads();
        if (tid < 64) {
            float s = (stS[tid] + stS[64+tid]) + (stS[128+tid] + stS[192+tid]);
            float q = (stQ[tid] + stQ[64+tid]) + (stQ[128+tid] + stQ[192+tid]);
            d_psum[yt*256 + n0 + tid] = s;
            d_psq [yt*256 + n0 + tid] = q;
        }
    }
}

// ---------------- prew + nodeagg: materialize w vectors, accumulate S_j, Q_j ----------------
__global__ void k_prew(const int* __restrict__ nbr_idx) {
    int c = threadIdx.x;
    int bj = blockIdx.x;
    int b = bj >> 7;
    int jrow = bj * NBR;
    float s = 0.f, q = 0.f;
    if (c < 128) {
        #pragma unroll
        for (int m = 0; m < NBR; m++) {
            int e = jrow + m;
            int pn = (b*AT + nbr_idx[e])*768;
            float w = d_PN[pn + 512 + c] + d_QE[e*512 + 256 + c];
            d_Wg[e*128 + c] = w;
            s += w; q = fmaf(w, w, q);
        }
    } else {
        int cc = c - 128;
        #pragma unroll
        for (int m = 0; m < NBR; m++) {
            int e = jrow + m;
            int pn = (b*AT + nbr_idx[e])*768;
            float w = d_PN[pn + 640 + cc] + d_QE[e*512 + 384 + cc];
            d_We[e*128 + cc] = w;
            s += w; q = fmaf(w, w, q);
        }
    }
    d_S[bj*256 + c] = s;
    d_Q[bj*256 + c] = q;
}

// ---------------- three-body pass 1 (closed form): 320 blocks x 32 rows ----------------
__global__ void k_pass1(const int* __restrict__ nbr_idx) {
    int c = threadIdx.x;
    float s = 0.f, q = 0.f;
    for (int i = 0; i < 32; i++) {
        int r = blockIdx.x*32 + i;
        int n = r % NBR;
        int ba = r / NBR;
        int b = ba >> 7;
        int j = nbr_idx[r];
        int bj = b*AT + j;
        int jrow = bj*NBR;
        float base = d_PN[ba*768 + c] + d_PN[bj*768 + 256 + c] + d_QE[r*512 + c];
        float wn = (c < 128) ? d_Wg[(jrow + n)*128 + c] : d_We[(jrow + n)*128 + c - 128];
        float Sm = d_S[bj*256 + c] - wn;
        float Qm = d_Q[bj*256 + c] - wn*wn;
        s += fmaf((float)NK, base, Sm);
        q += fmaf((float)NK*base + 2.f*Sm, base, Qm);
    }
    d_psum[OFF3 + blockIdx.x*256 + c] = s;
    d_psq [OFF3 + blockIdx.x*256 + c] = q;
}

// ---------------- BN finalize: 1024 threads = 32 part-rows x 32 lanes ----------------
__device__ __forceinline__ void fin_block(int c0,
        const float* __restrict__ ps, const float* __restrict__ pq,
        int ch, int parts, float cnt,
        const float* __restrict__ gamma, const float* __restrict__ beta,
        float* scale, float* shift) {
    __shared__ float sS[1024], sQ[1024];
    int tid = threadIdx.x;
    int lane = tid & 31, pr = tid >> 5;
    int c = c0 + lane;
    float s = 0.f, q = 0.f;
    for (int p = pr; p < parts; p += 32) {
        s += ps[p*ch + c];
        q += pq[p*ch + c];
    }
    sS[tid] = s; sQ[tid] = q;
    __syncthreads();
    if (tid < 512) { sS[tid] += sS[tid+512]; sQ[tid] += sQ[tid+512]; } __syncthreads();
    if (tid < 256) { sS[tid] += sS[tid+256]; sQ[tid] += sQ[tid+256]; } __syncthreads();
    if (tid < 128) { sS[tid] += sS[tid+128]; sQ[tid] += sQ[tid+128]; } __syncthreads();
    if (tid < 64)  { sS[tid] += sS[tid+64];  sQ[tid] += sQ[tid+64];  } __syncthreads();
    if (tid < 32) {
        s = sS[tid] + sS[tid+32];
        q = sQ[tid] + sQ[tid+32];
        float mean = s / cnt;
        float var  = q / cnt - mean*mean;
        float sc = gamma[c0 + tid] * rsqrtf(var + 1e-5f);
        scale[c0 + tid] = sc;
        shift[c0 + tid] = beta[c0 + tid] - mean * sc;
    }
}

// grid 16 x 1024: blocks 0..7 -> BN2 (parts=160), 8..15 -> BN3 (parts=320)
__global__ void __launch_bounds__(1024) k_fin23(
        const float* __restrict__ g2, const float* __restrict__ be2,
        const float* __restrict__ g3, const float* __restrict__ be3) {
    if (blockIdx.x < 8)
        fin_block(blockIdx.x*32, d_psum, d_psq, 256, 160, (float)R2, g2, be2, d_scale2, d_shift2);
    else
        fin_block((blockIdx.x-8)*32, d_psum + OFF3, d_psq + OFF3, 256, 320, (float)CNT3, g3, be3, d_scale3, d_shift3);
}

// grid 4 x 1024: final BN over 1280 parts of 128 channels
__global__ void __launch_bounds__(1024) k_finS(const float* __restrict__ gs, const float* __restrict__ bes) {
    fin_block(blockIdx.x*32, d_pSs, d_pSq, 128, 1280, (float)R2, gs, bes, d_scaleS, d_shiftS);
}

// ---------------- three-body pass 2: warp-per-row, float4, reads precomputed W ----------------
__global__ void __launch_bounds__(256) k_pass2(const int* __restrict__ nbr_idx) {
    __shared__ float sS[8][128];
    __shared__ float sQ[8][128];
    int wid = threadIdx.x >> 5, lane = threadIdx.x & 31;
    int r = blockIdx.x*8 + wid;
    int n = r % NBR;
    int ba = r / NBR;
    int b = ba >> 7;
    int j = nbr_idx[r];
    int bj = b*AT + j;
    int jrow = bj*NBR;
    int offW = 0;
    if (lane < NK) {
        int m = lane + (lane >= n);
        offW = (jrow + m)*128;
    }
    const float4* PNa = (const float4*)(d_PN + ba*768);
    const float4* PNj = (const float4*)(d_PN + bj*768);
    const float4* QEr = (const float4*)(d_QE + r*512);
    float4 sg = ((const float4*)d_scale3)[lane];
    float4 hg = ((const float4*)d_shift3)[lane];
    float4 se = ((const float4*)d_scale3)[32 + lane];
    float4 he = ((const float4*)d_shift3)[32 + lane];
    float4 pag = PNa[lane],      pjg = PNj[64 + lane], qeg = QEr[lane];
    float4 pae = PNa[32 + lane], pje = PNj[96 + lane], qee = QEr[32 + lane];
    float4 baseg, basee;
    baseg.x = fmaf(sg.x, pag.x + pjg.x + qeg.x, hg.x);
    baseg.y = fmaf(sg.y, pag.y + pjg.y + qeg.y, hg.y);
    baseg.z = fmaf(sg.z, pag.z + pjg.z + qeg.z, hg.z);
    baseg.w = fmaf(sg.w, pag.w + pjg.w + qeg.w, hg.w);
    basee.x = fmaf(se.x, pae.x + pje.x + qee.x, he.x);
    basee.y = fmaf(se.y, pae.y + pje.y + qee.y, he.y);
    basee.z = fmaf(se.z, pae.z + pje.z + qee.z, he.z);
    basee.w = fmaf(se.w, pae.w + pje.w + qee.w, he.w);

    float4 acc = make_float4(0.f, 0.f, 0.f, 0.f);
    #pragma unroll
    for (int k = 0; k < NK; k++) {
        int oW = __shfl_sync(0xffffffffu, offW, k);
        float4 wg = *(const float4*)(d_Wg + oW + 4*lane);
        float4 we = *(const float4*)(d_We + oW + 4*lane);
        float gx = fmaf(sg.x, wg.x, baseg.x);
        float gy = fmaf(sg.y, wg.y, baseg.y);
        float gz = fmaf(sg.z, wg.z, baseg.z);
        float gw = fmaf(sg.w, wg.w, baseg.w);
        float ex = fmaf(se.x, we.x, basee.x);
        float ey = fmaf(se.y, we.y, basee.y);
        float ez = fmaf(se.z, we.z, basee.z);
        float ew = fmaf(se.w, we.w, basee.w);
        acc.x += sigmoid_hw(gx) * tanh_hw(ex);
        acc.y += sigmoid_hw(gy) * tanh_hw(ey);
        acc.z += sigmoid_hw(gz) * tanh_hw(ez);
        acc.w += sigmoid_hw(gw) * tanh_hw(ew);
    }
    ((float4*)(d_TB + r*128))[lane] = acc;
    ((float4*)sS[wid])[lane] = acc;
    float4 a2 = make_float4(acc.x*acc.x, acc.y*acc.y, acc.z*acc.z, acc.w*acc.w);
    ((float4*)sQ[wid])[lane] = a2;
    __syncthreads();
    if (threadIdx.x < 128) {
        float s = 0.f, q = 0.f;
        #pragma unroll
        for (int w = 0; w < 8; w++) { s += sS[w][threadIdx.x]; q += sQ[w][threadIdx.x]; }
        d_pSs[blockIdx.x*128 + threadIdx.x] = s;
        d_pSq[blockIdx.x*128 + threadIdx.x] = q;
    }
}

// ---------------- final: out = tanh(edge + two_body + BN(three_body)), float4 + HW tanh ----------------
__global__ void k_out(const float* __restrict__ edge, float* __restrict__ out) {
    int idx = blockIdx.x*256 + threadIdx.x;
    if (idx >= R2*32) return;
    int cl = idx & 31;
    int r = idx >> 5;
    float4 yg = ((const float4*)d_Y2)[r*64 + cl];
    float4 ye = ((const float4*)d_Y2)[r*64 + 32 + cl];
    float4 tb = ((const float4*)d_TB)[idx];
    float4 eg = ((const float4*)edge)[idx];
    float4 s2g = ((const float4*)d_scale2)[cl],      h2g = ((const float4*)d_shift2)[cl];
    float4 s2e = ((const float4*)d_scale2)[32 + cl], h2e = ((const float4*)d_shift2)[32 + cl];
    float4 sS4 = ((const float4*)d_scaleS)[cl],      hS4 = ((const float4*)d_shiftS)[cl];
    float4 o;
    o.x = tanh_hw(eg.x + sigmoid_hw(fmaf(s2g.x, yg.x, h2g.x))*tanh_hw(fmaf(s2e.x, ye.x, h2e.x)) + fmaf(sS4.x, tb.x, hS4.x));
    o.y = tanh_hw(eg.y + sigmoid_hw(fmaf(s2g.y, yg.y, h2g.y))*tanh_hw(fmaf(s2e.y, ye.y, h2e.y)) + fmaf(sS4.y, tb.y, hS4.y));
    o.z = tanh_hw(eg.z + sigmoid_hw(fmaf(s2g.z, yg.z, h2g.z))*tanh_hw(fmaf(s2e.z, ye.z, h2e.z)) + fmaf(sS4.z, tb.z, hS4.z));
    o.w = tanh_hw(eg.w + sigmoid_hw(fmaf(s2g.w, yg.w, h2g.w))*tanh_hw(fmaf(s2e.w, ye.w, h2e.w)) + fmaf(sS4.w, tb.w, hS4.w));
    ((float4*)out)[idx] = o;
}

// ---------------- launch ----------------
extern "C" void kernel_launch(void* const* d_in, const int* in_sizes, int n_in,
                              void* d_out, int out_size) {
    const float* node     = (const float*)d_in[0];
    const float* edge     = (const float*)d_in[1];
    const int*   nbr_idx  = (const int*)  d_in[2];
    const int*   nbr_mask = (const int*)  d_in[3];
    const float* W2       = (const float*)d_in[4];
    const float* W3       = (const float*)d_in[6];
    const float* g2  = (const float*)d_in[8];
    const float* be2 = (const float*)d_in[9];
    const float* g3  = (const float*)d_in[10];
    const float* be3 = (const float*)d_in[11];
    const float* gs  = (const float*)d_in[12];
    const float* bes = (const float*)d_in[13];
    float* out = (float*)d_out;

    cudaFuncSetAttribute(gemm_all, cudaFuncAttributeMaxDynamicSharedMemorySize, GEMM_SMEM);

    // 0. pre-split B weights (tf32 hi/lo)
    k_split<<<768, 256>>>(W3, W2);

    // 1. all GEMMs (PN, QE, Y2 + fused BN2 stats), 3xTF32 with pre-split B
    gemm_all<<<dim3(12, 168), 256, GEMM_SMEM>>>(node, edge, nbr_idx, nbr_mask);

    // 2. materialize w vectors + per-node aggregates S_j, Q_j
    k_prew<<<NODES, 256>>>(nbr_idx);

    // 3. three-body pass 1 (closed-form BN3 stats, 320 partials)
    k_pass1<<<320, 256>>>(nbr_idx);

    // 4. finalize BN2 + BN3
    k_fin23<<<16, 1024>>>(g2, be2, g3, be3);

    // 5. three-body pass 2 (warp-per-row float4, reads W; fused final-BN stats)
    k_pass2<<<1280, 256>>>(nbr_idx);

    // 6. finalize final BN
    k_finS<<<4, 1024>>>(gs, bes);

    // 7. output (HW tanh)
    k_out<<<1280, 256>>>(edge, out);
}

// round 16
// speedup vs baseline: 1.1722x; 1.1722x over previous
#include <cuda_runtime.h>
#include <math.h>
#include <stdint.h>

#define Bsz 4
#define AT 128
#define NBR 20
#define NK 19
#define R2 (Bsz*AT*NBR)        // 10240 edge rows
#define NODES (Bsz*AT)         // 512
#define CNT3 (R2*NK)           // 194560 three-body rows
#define OFF3 (256*256)         // BN3 partial offset in d_psum/d_psq

// ---------------- scratch (static device globals; no allocation) ----------------
__device__ float d_Y2[R2*256];        // two-body pre-BN GEMM output
__device__ float d_PN[NODES*768];     // node @ [W3a|W3b|W3c]
__device__ float d_QE[R2*512];        // edge @ [W3d|W3e]
__device__ float d_TB[R2*128];        // three-body pre-final-BN sums
__device__ float d_Wg[R2*128];        // per-edge w gate part
__device__ float d_We[R2*128];        // per-edge w ext part
__device__ float d_S[NODES*256];      // per-node sum of w over its 20 neighbors
__device__ float d_Q[NODES*256];      // per-node sum of w^2
__device__ float d_psum[OFF3 + 1280*256];
__device__ float d_psq [OFF3 + 1280*256];
__device__ float d_pSs[1280*128];     // final-BN partials (from pass2 epilogue)
__device__ float d_pSq[1280*128];
__device__ float d_scale2[256], d_shift2[256];
__device__ float d_scale3[256], d_shift3[256];
__device__ float d_scaleS[128], d_shiftS[128];

__device__ __forceinline__ float tanh_hw(float x) {
    float y; asm("tanh.approx.f32 %0, %1;" : "=f"(y) : "f"(x)); return y;
}
__device__ __forceinline__ float sigmoid_hw(float x) {
    return fmaf(tanh_hw(0.5f*x), 0.5f, 0.5f);
}

// ---------------- tf32 helpers ----------------
__device__ __forceinline__ uint32_t f2tf32(float x) {
    uint32_t r; asm("cvt.rna.tf32.f32 %0, %1;" : "=r"(r) : "f"(x)); return r;
}
__device__ __forceinline__ void split_tf32(float x, uint32_t& hi, uint32_t& lo) {
    uint32_t h = f2tf32(x);
    hi = h;
    lo = f2tf32(x - __uint_as_float(h));
}
__device__ __forceinline__ void mma_tf32(float* d, const uint32_t* a, const uint32_t* b) {
    asm("mma.sync.aligned.m16n8k8.row.col.f32.tf32.tf32.f32 "
        "{%0,%1,%2,%3}, {%4,%5,%6,%7}, {%8,%9}, {%0,%1,%2,%3};"
        : "+f"(d[0]), "+f"(d[1]), "+f"(d[2]), "+f"(d[3])
        : "r"(a[0]), "r"(a[1]), "r"(a[2]), "r"(a[3]), "r"(b[0]), "r"(b[1]));
}

// ---------------- one fused GEMM launch for PN, QE, Y2 (3xTF32, R14-proven) ----------------
// grid (12, 168): yt<160,xt<8: QE | yt<160,xt>=8: Y2 (c2 fused) | yt>=160: PN
__global__ void __launch_bounds__(256) gemm_all(
    const float* __restrict__ node, const float* __restrict__ edge,
    const int* __restrict__ nbr_idx, const int* __restrict__ nbr_mask,
    const float* __restrict__ W2, const float* __restrict__ W3) {
    __shared__ float Ast[64][68];   // transposed: Ast[k][m]
    __shared__ float Bs[64][68];    // Bs[k][n]
    __shared__ int   sRI[64];
    __shared__ int   sRJ[64];
    __shared__ float sM[64];
    __shared__ float stS[4][64], stQ[4][64];
    int tid = threadIdx.x;
    int w = tid >> 5, lane = tid & 31;
    int wm = w >> 1, wn = w & 1;
    int gid = lane >> 2, tig = lane & 3;
    int xt = blockIdx.x, yt = blockIdx.y;

    const float* A; const float* Bp; float* C;
    int ldc, cbase, m0, n0, mode;
    if (yt >= 160) {                       // PN
        mode = 2; m0 = (yt - 160)*64; n0 = xt*64;
        A = node; Bp = W3 + (n0 >> 8)*(128*256); cbase = n0 & 255;
        C = d_PN; ldc = 768;
    } else if (xt < 8) {                   // QE
        mode = 0; m0 = yt*64; n0 = xt*64;
        A = edge; Bp = W3 + (3 + (n0 >> 8))*(128*256); cbase = n0 & 255;
        C = d_QE; ldc = 512;
    } else {                               // Y2 (c2 fused)
        mode = 1; m0 = yt*64; n0 = (xt - 8)*64;
        A = node; Bp = W2; cbase = n0;
        C = d_Y2; ldc = 256;
        if (tid < 64) {
            int r = m0 + tid;
            int j = nbr_idx[r];
            int b = r / (AT*NBR);
            sRI[tid] = (r / NBR)*128;
            sRJ[tid] = (b*AT + j)*128;
            sM[tid]  = (float)nbr_mask[r];
        }
        __syncthreads();
    }

    float acc[4][4] = {};   // [n-frag][c0..c3]
    for (int k0 = 0; k0 < 128; k0 += 64) {
        if (mode == 1) {
            #pragma unroll
            for (int l = 0; l < 4; l++) {
                int f = l*256 + tid;
                int m = f >> 4, k4 = (f & 15)*4;
                float4 vi = *(const float4*)&node[sRI[m] + k0 + k4];
                float4 vj = *(const float4*)&node[sRJ[m] + k0 + k4];
                float mm = sM[m];
                Ast[k4+0][m] = vi.x*vj.x*mm;
                Ast[k4+1][m] = vi.y*vj.y*mm;
                Ast[k4+2][m] = vi.z*vj.z*mm;
                Ast[k4+3][m] = vi.w*vj.w*mm;
            }
        } else {
            #pragma unroll
            for (int l = 0; l < 4; l++) {
                int f = l*256 + tid;
                int m = f >> 4, k4 = (f & 15)*4;
                float4 v = *(const float4*)&A[(m0 + m)*128 + k0 + k4];
                Ast[k4+0][m] = v.x;
                Ast[k4+1][m] = v.y;
                Ast[k4+2][m] = v.z;
                Ast[k4+3][m] = v.w;
            }
        }
        #pragma unroll
        for (int l = 0; l < 4; l++) {
            int f = l*256 + tid;
            int k = f >> 4, n4 = (f & 15)*4;
            *(float4*)&Bs[k][n4] = *(const float4*)&Bp[(k0 + k)*256 + cbase + n4];
        }
        __syncthreads();

        int mA = wm*16 + gid;
        #pragma unroll
        for (int k8 = 0; k8 < 64; k8 += 8) {
            uint32_t ah[4], al[4];
            split_tf32(Ast[k8+tig  ][mA  ], ah[0], al[0]);
            split_tf32(Ast[k8+tig  ][mA+8], ah[1], al[1]);
            split_tf32(Ast[k8+tig+4][mA  ], ah[2], al[2]);
            split_tf32(Ast[k8+tig+4][mA+8], ah[3], al[3]);
            #pragma unroll
            for (int f = 0; f < 4; f++) {
                int nB = wn*32 + f*8 + gid;
                uint32_t bh[2], bl[2];
                split_tf32(Bs[k8+tig  ][nB], bh[0], bl[0]);
                split_tf32(Bs[k8+tig+4][nB], bh[1], bl[1]);
                mma_tf32(acc[f], ah, bh);
                mma_tf32(acc[f], ah, bl);
                mma_tf32(acc[f], al, bh);
            }
        }
        __syncthreads();
    }

    // epilogue: scattered float2 stores
    {
        int mrow = m0 + wm*16 + gid;
        #pragma unroll
        for (int f = 0; f < 4; f++) {
            int ncol = n0 + wn*32 + f*8 + 2*tig;
            *(float2*)&C[ mrow   *ldc + ncol] = make_float2(acc[f][0], acc[f][1]);
            *(float2*)&C[(mrow+8)*ldc + ncol] = make_float2(acc[f][2], acc[f][3]);
        }
    }

    // fused BN2 tile stats (Y2 tiles only)
    if (mode == 1) {
        #pragma unroll
        for (int f = 0; f < 4; f++) {
            float s0 = acc[f][0] + acc[f][2];
            float s1 = acc[f][1] + acc[f][3];
            float q0 = acc[f][0]*acc[f][0] + acc[f][2]*acc[f][2];
            float q1 = acc[f][1]*acc[f][1] + acc[f][3]*acc[f][3];
            #pragma unroll
            for (int off = 4; off < 32; off <<= 1) {
                s0 += __shfl_xor_sync(0xffffffffu, s0, off);
                s1 += __shfl_xor_sync(0xffffffffu, s1, off);
                q0 += __shfl_xor_sync(0xffffffffu, q0, off);
                q1 += __shfl_xor_sync(0xffffffffu, q1, off);
            }
            if (gid == 0) {
                int nc = wn*32 + f*8 + 2*tig;
                stS[wm][nc] = s0; stS[wm][nc+1] = s1;
                stQ[wm][nc] = q0; stQ[wm][nc+1] = q1;
            }
        }
        __syncthreads();
        if (tid < 64) {
            float s = (stS[0][tid] + stS[1][tid]) + (stS[2][tid] + stS[3][tid]);
            float q = (stQ[0][tid] + stQ[1][tid]) + (stQ[2][tid] + stQ[3][tid]);
            d_psum[yt*256 + n0 + tid] = s;
            d_psq [yt*256 + n0 + tid] = q;
        }
    }
}

// ---------------- prew + nodeagg: materialize w vectors, accumulate S_j, Q_j ----------------
__global__ void k_prew(const int* __restrict__ nbr_idx) {
    int c = threadIdx.x;
    int bj = blockIdx.x;
    int b = bj >> 7;
    int jrow = bj * NBR;
    float s = 0.f, q = 0.f;
    if (c < 128) {
        #pragma unroll
        for (int m = 0; m < NBR; m++) {
            int e = jrow + m;
            int pn = (b*AT + nbr_idx[e])*768;
            float w = d_PN[pn + 512 + c] + d_QE[e*512 + 256 + c];
            d_Wg[e*128 + c] = w;
            s += w; q = fmaf(w, w, q);
        }
    } else {
        int cc = c - 128;
        #pragma unroll
        for (int m = 0; m < NBR; m++) {
            int e = jrow + m;
            int pn = (b*AT + nbr_idx[e])*768;
            float w = d_PN[pn + 640 + cc] + d_QE[e*512 + 384 + cc];
            d_We[e*128 + cc] = w;
            s += w; q = fmaf(w, w, q);
        }
    }
    d_S[bj*256 + c] = s;
    d_Q[bj*256 + c] = q;
}

// ---------------- three-body pass 1 (closed form): warp-per-row, float4 ----------------
// grid 1280 x 256 (8 warps = 8 rows); lane owns 4 gate channels (4l) + 4 ext channels (128+4l)
__global__ void __launch_bounds__(256) k_pass1(const int* __restrict__ nbr_idx) {
    __shared__ float sS[8][256];
    __shared__ float sQ[8][256];
    int wid = threadIdx.x >> 5, lane = threadIdx.x & 31;
    int r = blockIdx.x*8 + wid;
    int n = r % NBR;
    int ba = r / NBR;
    int b = ba >> 7;
    int j = nbr_idx[r];
    int bj = b*AT + j;
    int jrow = bj*NBR;

    const float* PNa = d_PN + ba*768;
    const float* PNj = d_PN + bj*768;
    const float* QEr = d_QE + r*512;
    int c4 = 4*lane;

    // gate half (channels c4..c4+3)
    float4 ag = *(const float4*)(PNa + c4);
    float4 jg = *(const float4*)(PNj + 256 + c4);
    float4 qg = *(const float4*)(QEr + c4);
    float4 wng = *(const float4*)(d_Wg + (jrow + n)*128 + c4);
    float4 Sg = *(const float4*)(d_S + bj*256 + c4);
    float4 Qg = *(const float4*)(d_Q + bj*256 + c4);
    // ext half (channels 128+c4 ..)
    float4 ae = *(const float4*)(PNa + 128 + c4);
    float4 je = *(const float4*)(PNj + 384 + c4);
    float4 qe = *(const float4*)(QEr + 128 + c4);
    float4 wne = *(const float4*)(d_We + (jrow + n)*128 + c4);
    float4 Se = *(const float4*)(d_S + bj*256 + 128 + c4);
    float4 Qe = *(const float4*)(d_Q + bj*256 + 128 + c4);

    const float NKf = (float)NK;
    #define P1(base_, wn_, S_, Q_, sc, qc) { \
        float base = base_; \
        float Sm = S_ - wn_; \
        float Qm = Q_ - wn_*wn_; \
        sc = fmaf(NKf, base, Sm); \
        qc = fmaf(NKf*base + 2.f*Sm, base, Qm); }

    float s0,s1,s2,s3,q0,q1,q2,q3;
    P1(ag.x+jg.x+qg.x, wng.x, Sg.x, Qg.x, s0, q0);
    P1(ag.y+jg.y+qg.y, wng.y, Sg.y, Qg.y, s1, q1);
    P1(ag.z+jg.z+qg.z, wng.z, Sg.z, Qg.z, s2, q2);
    P1(ag.w+jg.w+qg.w, wng.w, Sg.w, Qg.w, s3, q3);
    *(float4*)&sS[wid][c4] = make_float4(s0,s1,s2,s3);
    *(float4*)&sQ[wid][c4] = make_float4(q0,q1,q2,q3);
    P1(ae.x+je.x+qe.x, wne.x, Se.x, Qe.x, s0, q0);
    P1(ae.y+je.y+qe.y, wne.y, Se.y, Qe.y, s1, q1);
    P1(ae.z+je.z+qe.z, wne.z, Se.z, Qe.z, s2, q2);
    P1(ae.w+je.w+qe.w, wne.w, Se.w, Qe.w, s3, q3);
    *(float4*)&sS[wid][128 + c4] = make_float4(s0,s1,s2,s3);
    *(float4*)&sQ[wid][128 + c4] = make_float4(q0,q1,q2,q3);
    #undef P1
    __syncthreads();

    int c = threadIdx.x;    // 256 channels
    float s = 0.f, q = 0.f;
    #pragma unroll
    for (int ww = 0; ww < 8; ww++) { s += sS[ww][c]; q += sQ[ww][c]; }
    d_psum[OFF3 + blockIdx.x*256 + c] = s;
    d_psq [OFF3 + blockIdx.x*256 + c] = q;
}

// ---------------- BN finalize: 1024 threads = 32 part-rows x 32 lanes ----------------
__device__ __forceinline__ void fin_block(int c0,
        const float* __restrict__ ps, const float* __restrict__ pq,
        int ch, int parts, float cnt,
        const float* __restrict__ gamma, const float* __restrict__ beta,
        float* scale, float* shift) {
    __shared__ float sS[1024], sQ[1024];
    int tid = threadIdx.x;
    int lane = tid & 31, pr = tid >> 5;
    int c = c0 + lane;
    float s = 0.f, q = 0.f;
    for (int p = pr; p < parts; p += 32) {
        s += ps[p*ch + c];
        q += pq[p*ch + c];
    }
    sS[tid] = s; sQ[tid] = q;
    __syncthreads();
    if (tid < 512) { sS[tid] += sS[tid+512]; sQ[tid] += sQ[tid+512]; } __syncthreads();
    if (tid < 256) { sS[tid] += sS[tid+256]; sQ[tid] += sQ[tid+256]; } __syncthreads();
    if (tid < 128) { sS[tid] += sS[tid+128]; sQ[tid] += sQ[tid+128]; } __syncthreads();
    if (tid < 64)  { sS[tid] += sS[tid+64];  sQ[tid] += sQ[tid+64];  } __syncthreads();
    if (tid < 32) {
        s = sS[tid] + sS[tid+32];
        q = sQ[tid] + sQ[tid+32];
        float mean = s / cnt;
        float var  = q / cnt - mean*mean;
        float sc = gamma[c0 + tid] * rsqrtf(var + 1e-5f);
        scale[c0 + tid] = sc;
        shift[c0 + tid] = beta[c0 + tid] - mean * sc;
    }
}

// grid 16 x 1024: blocks 0..7 -> BN2 (parts=160), 8..15 -> BN3 (parts=1280)
__global__ void __launch_bounds__(1024) k_fin23(
        const float* __restrict__ g2, const float* __restrict__ be2,
        const float* __restrict__ g3, const float* __restrict__ be3) {
    if (blockIdx.x < 8)
        fin_block(blockIdx.x*32, d_psum, d_psq, 256, 160, (float)R2, g2, be2, d_scale2, d_shift2);
    else
        fin_block((blockIdx.x-8)*32, d_psum + OFF3, d_psq + OFF3, 256, 1280, (float)CNT3, g3, be3, d_scale3, d_shift3);
}

// grid 4 x 1024: final BN over 1280 parts of 128 channels
__global__ void __launch_bounds__(1024) k_finS(const float* __restrict__ gs, const float* __restrict__ bes) {
    fin_block(blockIdx.x*32, d_pSs, d_pSq, 128, 1280, (float)R2, gs, bes, d_scaleS, d_shiftS);
}

// ---------------- three-body pass 2: warp-per-row, float4, reads precomputed W ----------------
__global__ void __launch_bounds__(256) k_pass2(const int* __restrict__ nbr_idx) {
    __shared__ float sS[8][128];
    __shared__ float sQ[8][128];
    int wid = threadIdx.x >> 5, lane = threadIdx.x & 31;
    int r = blockIdx.x*8 + wid;
    int n = r % NBR;
    int ba = r / NBR;
    int b = ba >> 7;
    int j = nbr_idx[r];
    int bj = b*AT + j;
    int jrow = bj*NBR;
    int offW = 0;
    if (lane < NK) {
        int m = lane + (lane >= n);
        offW = (jrow + m)*128;
    }
    const float4* PNa = (const float4*)(d_PN + ba*768);
    const float4* PNj = (const float4*)(d_PN + bj*768);
    const float4* QEr = (const float4*)(d_QE + r*512);
    float4 sg = ((const float4*)d_scale3)[lane];
    float4 hg = ((const float4*)d_shift3)[lane];
    float4 se = ((const float4*)d_scale3)[32 + lane];
    float4 he = ((const float4*)d_shift3)[32 + lane];
    float4 pag = PNa[lane],      pjg = PNj[64 + lane], qeg = QEr[lane];
    float4 pae = PNa[32 + lane], pje = PNj[96 + lane], qee = QEr[32 + lane];
    float4 baseg, basee;
    baseg.x = fmaf(sg.x, pag.x + pjg.x + qeg.x, hg.x);
    baseg.y = fmaf(sg.y, pag.y + pjg.y + qeg.y, hg.y);
    baseg.z = fmaf(sg.z, pag.z + pjg.z + qeg.z, hg.z);
    baseg.w = fmaf(sg.w, pag.w + pjg.w + qeg.w, hg.w);
    basee.x = fmaf(se.x, pae.x + pje.x + qee.x, he.x);
    basee.y = fmaf(se.y, pae.y + pje.y + qee.y, he.y);
    basee.z = fmaf(se.z, pae.z + pje.z + qee.z, he.z);
    basee.w = fmaf(se.w, pae.w + pje.w + qee.w, he.w);

    float4 acc = make_float4(0.f, 0.f, 0.f, 0.f);
    #pragma unroll
    for (int k = 0; k < NK; k++) {
        int oW = __shfl_sync(0xffffffffu, offW, k);
        float4 wg = *(const float4*)(d_Wg + oW + 4*lane);
        float4 we = *(const float4*)(d_We + oW + 4*lane);
        float gx = fmaf(sg.x, wg.x, baseg.x);
        float gy = fmaf(sg.y, wg.y, baseg.y);
        float gz = fmaf(sg.z, wg.z, baseg.z);
        float gw = fmaf(sg.w, wg.w, baseg.w);
        float ex = fmaf(se.x, we.x, basee.x);
        float ey = fmaf(se.y, we.y, basee.y);
        float ez = fmaf(se.z, we.z, basee.z);
        float ew = fmaf(se.w, we.w, basee.w);
        acc.x += sigmoid_hw(gx) * tanh_hw(ex);
        acc.y += sigmoid_hw(gy) * tanh_hw(ey);
        acc.z += sigmoid_hw(gz) * tanh_hw(ez);
        acc.w += sigmoid_hw(gw) * tanh_hw(ew);
    }
    ((float4*)(d_TB + r*128))[lane] = acc;
    ((float4*)sS[wid])[lane] = acc;
    float4 a2 = make_float4(acc.x*acc.x, acc.y*acc.y, acc.z*acc.z, acc.w*acc.w);
    ((float4*)sQ[wid])[lane] = a2;
    __syncthreads();
    if (threadIdx.x < 128) {
        float s = 0.f, q = 0.f;
        #pragma unroll
        for (int w = 0; w < 8; w++) { s += sS[w][threadIdx.x]; q += sQ[w][threadIdx.x]; }
        d_pSs[blockIdx.x*128 + threadIdx.x] = s;
        d_pSq[blockIdx.x*128 + threadIdx.x] = q;
    }
}

// ---------------- final: out = tanh(edge + two_body + BN(three_body)), float4 + HW tanh ----------------
__global__ void k_out(const float* __restrict__ edge, float* __restrict__ out) {
    int idx = blockIdx.x*256 + threadIdx.x;
    if (idx >= R2*32) return;
    int cl = idx & 31;
    int r = idx >> 5;
    float4 yg = ((const float4*)d_Y2)[r*64 + cl];
    float4 ye = ((const float4*)d_Y2)[r*64 + 32 + cl];
    float4 tb = ((const float4*)d_TB)[idx];
    float4 eg = ((const float4*)edge)[idx];
    float4 s2g = ((const float4*)d_scale2)[cl],      h2g = ((const float4*)d_shift2)[cl];
    float4 s2e = ((const float4*)d_scale2)[32 + cl], h2e = ((const float4*)d_shift2)[32 + cl];
    float4 sS4 = ((const float4*)d_scaleS)[cl],      hS4 = ((const float4*)d_shiftS)[cl];
    float4 o;
    o.x = tanh_hw(eg.x + sigmoid_hw(fmaf(s2g.x, yg.x, h2g.x))*tanh_hw(fmaf(s2e.x, ye.x, h2e.x)) + fmaf(sS4.x, tb.x, hS4.x));
    o.y = tanh_hw(eg.y + sigmoid_hw(fmaf(s2g.y, yg.y, h2g.y))*tanh_hw(fmaf(s2e.y, ye.y, h2e.y)) + fmaf(sS4.y, tb.y, hS4.y));
    o.z = tanh_hw(eg.z + sigmoid_hw(fmaf(s2g.z, yg.z, h2g.z))*tanh_hw(fmaf(s2e.z, ye.z, h2e.z)) + fmaf(sS4.z, tb.z, hS4.z));
    o.w = tanh_hw(eg.w + sigmoid_hw(fmaf(s2g.w, yg.w, h2g.w))*tanh_hw(fmaf(s2e.w, ye.w, h2e.w)) + fmaf(sS4.w, tb.w, hS4.w));
    ((float4*)out)[idx] = o;
}

// ---------------- launch ----------------
extern "C" void kernel_launch(void* const* d_in, const int* in_sizes, int n_in,
                              void* d_out, int out_size) {
    const float* node     = (const float*)d_in[0];
    const float* edge     = (const float*)d_in[1];
    const int*   nbr_idx  = (const int*)  d_in[2];
    const int*   nbr_mask = (const int*)  d_in[3];
    const float* W2       = (const float*)d_in[4];
    const float* W3       = (const float*)d_in[6];
    const float* g2  = (const float*)d_in[8];
    const float* be2 = (const float*)d_in[9];
    const float* g3  = (const float*)d_in[10];
    const float* be3 = (const float*)d_in[11];
    const float* gs  = (const float*)d_in[12];
    const float* bes = (const float*)d_in[13];
    float* out = (float*)d_out;

    // 1. all GEMMs (PN, QE, Y2 + fused BN2 stats), R14-proven 3xTF32
    gemm_all<<<dim3(12, 168), 256>>>(node, edge, nbr_idx, nbr_mask, W2, W3);

    // 2. materialize w vectors + per-node aggregates S_j, Q_j
    k_prew<<<NODES, 256>>>(nbr_idx);

    // 3. three-body pass 1 (closed-form, warp-per-row float4, 1280 partials)
    k_pass1<<<1280, 256>>>(nbr_idx);

    // 4. finalize BN2 + BN3
    k_fin23<<<16, 1024>>>(g2, be2, g3, be3);

    // 5. three-body pass 2 (warp-per-row float4, reads W; fused final-BN stats)
    k_pass2<<<1280, 256>>>(nbr_idx);

    // 6. finalize final BN
    k_finS<<<4, 1024>>>(gs, bes);

    // 7. output (HW tanh)
    k_out<<<1280, 256>>>(edge, out);
}

// round 17
// speedup vs baseline: 1.2634x; 1.0778x over previous
#include <cuda_runtime.h>
#include <math.h>
#include <stdint.h>

#define Bsz 4
#define AT 128
#define NBR 20
#define NK 19
#define R2 (Bsz*AT*NBR)        // 10240 edge rows
#define NODES (Bsz*AT)         // 512
#define CNT3 (R2*NK)           // 194560 three-body rows
#define OFF3 (256*256)         // BN3 partial offset in d_psum/d_psq

// ---------------- scratch (static device globals; no allocation) ----------------
__device__ float d_Y2[R2*256];        // two-body pre-BN GEMM output
__device__ float d_PN[NODES*768];     // node @ [W3a|W3b|W3c]
__device__ float d_QE[R2*512];        // edge @ [W3d|W3e]
__device__ float d_TB[R2*128];        // three-body pre-final-BN sums
__device__ float d_Wg[R2*128];        // per-edge w gate part
__device__ float d_We[R2*128];        // per-edge w ext part
__device__ float d_S[NODES*256];      // per-node sum of w over its 20 neighbors
__device__ float d_Q[NODES*256];      // per-node sum of w^2
__device__ float d_psum[OFF3 + 1280*256];
__device__ float d_psq [OFF3 + 1280*256];
__device__ float d_pSs[1280*128];     // final-BN partials (from pass2 epilogue)
__device__ float d_pSq[1280*128];
__device__ float d_scale2[256], d_shift2[256];
__device__ float d_scale3[256], d_shift3[256];
__device__ float d_scaleS[128], d_shiftS[128];

__device__ __forceinline__ float tanh_hw(float x) {
    float y; asm("tanh.approx.f32 %0, %1;" : "=f"(y) : "f"(x)); return y;
}
__device__ __forceinline__ float sigmoid_hw(float x) {
    return fmaf(tanh_hw(0.5f*x), 0.5f, 0.5f);
}

// ---------------- tf32 helpers ----------------
__device__ __forceinline__ uint32_t f2tf32(float x) {
    uint32_t r; asm("cvt.rna.tf32.f32 %0, %1;" : "=r"(r) : "f"(x)); return r;
}
__device__ __forceinline__ void split_tf32(float x, uint32_t& hi, uint32_t& lo) {
    uint32_t h = f2tf32(x);
    hi = h;
    lo = f2tf32(x - __uint_as_float(h));
}
__device__ __forceinline__ void mma_tf32(float* d, const uint32_t* a, const uint32_t* b) {
    asm("mma.sync.aligned.m16n8k8.row.col.f32.tf32.tf32.f32 "
        "{%0,%1,%2,%3}, {%4,%5,%6,%7}, {%8,%9}, {%0,%1,%2,%3};"
        : "+f"(d[0]), "+f"(d[1]), "+f"(d[2]), "+f"(d[3])
        : "r"(a[0]), "r"(a[1]), "r"(a[2]), "r"(a[3]), "r"(b[0]), "r"(b[1]));
}

// ---------------- one fused GEMM launch for PN, QE, Y2 (3xTF32, k-chunk 32) ----------------
// grid (12, 168): yt<160,xt<8: QE | yt<160,xt>=8: Y2 (c2 fused) | yt>=160: PN
// 8 warps = 4(M) x 2(N); warp tile 16x32 via mma.m16n8k8 with hi/lo tf32 split.
// smem per block ~19.5KB -> 2-3 blocks/SM for latency hiding.
__global__ void __launch_bounds__(256) gemm_all(
    const float* __restrict__ node, const float* __restrict__ edge,
    const int* __restrict__ nbr_idx, const int* __restrict__ nbr_mask,
    const float* __restrict__ W2, const float* __restrict__ W3) {
    __shared__ float Ast[32][68];   // transposed: Ast[k][m]
    __shared__ float Bs[32][68];    // Bs[k][n]
    __shared__ int   sRI[64];
    __shared__ int   sRJ[64];
    __shared__ float sM[64];
    __shared__ float stS[4][64], stQ[4][64];
    int tid = threadIdx.x;
    int w = tid >> 5, lane = tid & 31;
    int wm = w >> 1, wn = w & 1;
    int gid = lane >> 2, tig = lane & 3;
    int xt = blockIdx.x, yt = blockIdx.y;

    const float* A; const float* Bp; float* C;
    int ldc, cbase, m0, n0, mode;
    if (yt >= 160) {                       // PN
        mode = 2; m0 = (yt - 160)*64; n0 = xt*64;
        A = node; Bp = W3 + (n0 >> 8)*(128*256); cbase = n0 & 255;
        C = d_PN; ldc = 768;
    } else if (xt < 8) {                   // QE
        mode = 0; m0 = yt*64; n0 = xt*64;
        A = edge; Bp = W3 + (3 + (n0 >> 8))*(128*256); cbase = n0 & 255;
        C = d_QE; ldc = 512;
    } else {                               // Y2 (c2 fused)
        mode = 1; m0 = yt*64; n0 = (xt - 8)*64;
        A = node; Bp = W2; cbase = n0;
        C = d_Y2; ldc = 256;
        if (tid < 64) {
            int r = m0 + tid;
            int j = nbr_idx[r];
            int b = r / (AT*NBR);
            sRI[tid] = (r / NBR)*128;
            sRJ[tid] = (b*AT + j)*128;
            sM[tid]  = (float)nbr_mask[r];
        }
        __syncthreads();
    }

    float acc[4][4] = {};   // [n-frag][c0..c3]
    for (int k0 = 0; k0 < 128; k0 += 32) {
        // A tile: 64 m x 32 k -> Ast[k][m]; 512 float4 = 2/thread
        if (mode == 1) {
            #pragma unroll
            for (int l = 0; l < 2; l++) {
                int f = l*256 + tid;
                int m = f >> 3, k4 = (f & 7)*4;
                float4 vi = *(const float4*)&node[sRI[m] + k0 + k4];
                float4 vj = *(const float4*)&node[sRJ[m] + k0 + k4];
                float mm = sM[m];
                Ast[k4+0][m] = vi.x*vj.x*mm;
                Ast[k4+1][m] = vi.y*vj.y*mm;
                Ast[k4+2][m] = vi.z*vj.z*mm;
                Ast[k4+3][m] = vi.w*vj.w*mm;
            }
        } else {
            #pragma unroll
            for (int l = 0; l < 2; l++) {
                int f = l*256 + tid;
                int m = f >> 3, k4 = (f & 7)*4;
                float4 v = *(const float4*)&A[(m0 + m)*128 + k0 + k4];
                Ast[k4+0][m] = v.x;
                Ast[k4+1][m] = v.y;
                Ast[k4+2][m] = v.z;
                Ast[k4+3][m] = v.w;
            }
        }
        // B tile: 32 k x 64 n; 512 float4 = 2/thread
        #pragma unroll
        for (int l = 0; l < 2; l++) {
            int f = l*256 + tid;
            int k = f >> 4, n4 = (f & 15)*4;
            *(float4*)&Bs[k][n4] = *(const float4*)&Bp[(k0 + k)*256 + cbase + n4];
        }
        __syncthreads();

        int mA = wm*16 + gid;
        #pragma unroll
        for (int k8 = 0; k8 < 32; k8 += 8) {
            uint32_t ah[4], al[4];
            split_tf32(Ast[k8+tig  ][mA  ], ah[0], al[0]);
            split_tf32(Ast[k8+tig  ][mA+8], ah[1], al[1]);
            split_tf32(Ast[k8+tig+4][mA  ], ah[2], al[2]);
            split_tf32(Ast[k8+tig+4][mA+8], ah[3], al[3]);
            #pragma unroll
            for (int f = 0; f < 4; f++) {
                int nB = wn*32 + f*8 + gid;
                uint32_t bh[2], bl[2];
                split_tf32(Bs[k8+tig  ][nB], bh[0], bl[0]);
                split_tf32(Bs[k8+tig+4][nB], bh[1], bl[1]);
                mma_tf32(acc[f], ah, bh);
                mma_tf32(acc[f], ah, bl);
                mma_tf32(acc[f], al, bh);
            }
        }
        __syncthreads();
    }

    // epilogue: scattered float2 stores
    {
        int mrow = m0 + wm*16 + gid;
        #pragma unroll
        for (int f = 0; f < 4; f++) {
            int ncol = n0 + wn*32 + f*8 + 2*tig;
            *(float2*)&C[ mrow   *ldc + ncol] = make_float2(acc[f][0], acc[f][1]);
            *(float2*)&C[(mrow+8)*ldc + ncol] = make_float2(acc[f][2], acc[f][3]);
        }
    }

    // fused BN2 tile stats (Y2 tiles only)
    if (mode == 1) {
        #pragma unroll
        for (int f = 0; f < 4; f++) {
            float s0 = acc[f][0] + acc[f][2];
            float s1 = acc[f][1] + acc[f][3];
            float q0 = acc[f][0]*acc[f][0] + acc[f][2]*acc[f][2];
            float q1 = acc[f][1]*acc[f][1] + acc[f][3]*acc[f][3];
            #pragma unroll
            for (int off = 4; off < 32; off <<= 1) {
                s0 += __shfl_xor_sync(0xffffffffu, s0, off);
                s1 += __shfl_xor_sync(0xffffffffu, s1, off);
                q0 += __shfl_xor_sync(0xffffffffu, q0, off);
                q1 += __shfl_xor_sync(0xffffffffu, q1, off);
            }
            if (gid == 0) {
                int nc = wn*32 + f*8 + 2*tig;
                stS[wm][nc] = s0; stS[wm][nc+1] = s1;
                stQ[wm][nc] = q0; stQ[wm][nc+1] = q1;
            }
        }
        __syncthreads();
        if (tid < 64) {
            float s = (stS[0][tid] + stS[1][tid]) + (stS[2][tid] + stS[3][tid]);
            float q = (stQ[0][tid] + stQ[1][tid]) + (stQ[2][tid] + stQ[3][tid]);
            d_psum[yt*256 + n0 + tid] = s;
            d_psq [yt*256 + n0 + tid] = q;
        }
    }
}

// ---------------- prew + nodeagg: materialize w vectors, accumulate S_j, Q_j ----------------
__global__ void k_prew(const int* __restrict__ nbr_idx) {
    int c = threadIdx.x;
    int bj = blockIdx.x;
    int b = bj >> 7;
    int jrow = bj * NBR;
    float s = 0.f, q = 0.f;
    if (c < 128) {
        #pragma unroll
        for (int m = 0; m < NBR; m++) {
            int e = jrow + m;
            int pn = (b*AT + nbr_idx[e])*768;
            float w = d_PN[pn + 512 + c] + d_QE[e*512 + 256 + c];
            d_Wg[e*128 + c] = w;
            s += w; q = fmaf(w, w, q);
        }
    } else {
        int cc = c - 128;
        #pragma unroll
        for (int m = 0; m < NBR; m++) {
            int e = jrow + m;
            int pn = (b*AT + nbr_idx[e])*768;
            float w = d_PN[pn + 640 + cc] + d_QE[e*512 + 384 + cc];
            d_We[e*128 + cc] = w;
            s += w; q = fmaf(w, w, q);
        }
    }
    d_S[bj*256 + c] = s;
    d_Q[bj*256 + c] = q;
}

// ---------------- three-body pass 1 (closed form): warp-per-4-rows, float4 ----------------
// grid 320 x 256 (8 warps x 4 rows); lane owns 4 gate + 4 ext channels
__global__ void __launch_bounds__(256) k_pass1(const int* __restrict__ nbr_idx) {
    __shared__ float sS[8][256];
    __shared__ float sQ[8][256];
    int wid = threadIdx.x >> 5, lane = threadIdx.x & 31;
    int c4 = 4*lane;
    const float NKf = (float)NK;

    float4 aSg = make_float4(0,0,0,0), aQg = aSg, aSe = aSg, aQe = aSg;
    #pragma unroll
    for (int i = 0; i < 4; i++) {
        int r = blockIdx.x*32 + wid*4 + i;
        int n = r % NBR;
        int ba = r / NBR;
        int b = ba >> 7;
        int j = nbr_idx[r];
        int bj = b*AT + j;
        int jrow = bj*NBR;
        const float* PNa = d_PN + ba*768;
        const float* PNj = d_PN + bj*768;
        const float* QEr = d_QE + r*512;

        float4 ag = *(const float4*)(PNa + c4);
        float4 jg = *(const float4*)(PNj + 256 + c4);
        float4 qg = *(const float4*)(QEr + c4);
        float4 wng = *(const float4*)(d_Wg + (jrow + n)*128 + c4);
        float4 Sg = *(const float4*)(d_S + bj*256 + c4);
        float4 Qg = *(const float4*)(d_Q + bj*256 + c4);
        float4 ae = *(const float4*)(PNa + 128 + c4);
        float4 je = *(const float4*)(PNj + 384 + c4);
        float4 qe = *(const float4*)(QEr + 128 + c4);
        float4 wne = *(const float4*)(d_We + (jrow + n)*128 + c4);
        float4 Se = *(const float4*)(d_S + bj*256 + 128 + c4);
        float4 Qe = *(const float4*)(d_Q + bj*256 + 128 + c4);

        #define P1(base_, wn_, S_, Q_, sc, qc) { \
            float base = base_; \
            float Sm = S_ - wn_; \
            float Qm = Q_ - wn_*wn_; \
            sc += fmaf(NKf, base, Sm); \
            qc += fmaf(NKf*base + 2.f*Sm, base, Qm); }
        P1(ag.x+jg.x+qg.x, wng.x, Sg.x, Qg.x, aSg.x, aQg.x);
        P1(ag.y+jg.y+qg.y, wng.y, Sg.y, Qg.y, aSg.y, aQg.y);
        P1(ag.z+jg.z+qg.z, wng.z, Sg.z, Qg.z, aSg.z, aQg.z);
        P1(ag.w+jg.w+qg.w, wng.w, Sg.w, Qg.w, aSg.w, aQg.w);
        P1(ae.x+je.x+qe.x, wne.x, Se.x, Qe.x, aSe.x, aQe.x);
        P1(ae.y+je.y+qe.y, wne.y, Se.y, Qe.y, aSe.y, aQe.y);
        P1(ae.z+je.z+qe.z, wne.z, Se.z, Qe.z, aSe.z, aQe.z);
        P1(ae.w+je.w+qe.w, wne.w, Se.w, Qe.w, aSe.w, aQe.w);
        #undef P1
    }
    *(float4*)&sS[wid][c4]       = aSg;
    *(float4*)&sQ[wid][c4]       = aQg;
    *(float4*)&sS[wid][128 + c4] = aSe;
    *(float4*)&sQ[wid][128 + c4] = aQe;
    __syncthreads();

    int c = threadIdx.x;
    float s = 0.f, q = 0.f;
    #pragma unroll
    for (int ww = 0; ww < 8; ww++) { s += sS[ww][c]; q += sQ[ww][c]; }
    d_psum[OFF3 + blockIdx.x*256 + c] = s;
    d_psq [OFF3 + blockIdx.x*256 + c] = q;
}

// ---------------- BN finalize: 1024 threads = 32 part-rows x 32 lanes ----------------
__device__ __forceinline__ void fin_block(int c0,
        const float* __restrict__ ps, const float* __restrict__ pq,
        int ch, int parts, float cnt,
        const float* __restrict__ gamma, const float* __restrict__ beta,
        float* scale, float* shift) {
    __shared__ float sS[1024], sQ[1024];
    int tid = threadIdx.x;
    int lane = tid & 31, pr = tid >> 5;
    int c = c0 + lane;
    float s = 0.f, q = 0.f;
    for (int p = pr; p < parts; p += 32) {
        s += ps[p*ch + c];
        q += pq[p*ch + c];
    }
    sS[tid] = s; sQ[tid] = q;
    __syncthreads();
    if (tid < 512) { sS[tid] += sS[tid+512]; sQ[tid] += sQ[tid+512]; } __syncthreads();
    if (tid < 256) { sS[tid] += sS[tid+256]; sQ[tid] += sQ[tid+256]; } __syncthreads();
    if (tid < 128) { sS[tid] += sS[tid+128]; sQ[tid] += sQ[tid+128]; } __syncthreads();
    if (tid < 64)  { sS[tid] += sS[tid+64];  sQ[tid] += sQ[tid+64];  } __syncthreads();
    if (tid < 32) {
        s = sS[tid] + sS[tid+32];
        q = sQ[tid] + sQ[tid+32];
        float mean = s / cnt;
        float var  = q / cnt - mean*mean;
        float sc = gamma[c0 + tid] * rsqrtf(var + 1e-5f);
        scale[c0 + tid] = sc;
        shift[c0 + tid] = beta[c0 + tid] - mean * sc;
    }
}

// grid 16 x 1024: blocks 0..7 -> BN2 (parts=160), 8..15 -> BN3 (parts=320)
__global__ void __launch_bounds__(1024) k_fin23(
        const float* __restrict__ g2, const float* __restrict__ be2,
        const float* __restrict__ g3, const float* __restrict__ be3) {
    if (blockIdx.x < 8)
        fin_block(blockIdx.x*32, d_psum, d_psq, 256, 160, (float)R2, g2, be2, d_scale2, d_shift2);
    else
        fin_block((blockIdx.x-8)*32, d_psum + OFF3, d_psq + OFF3, 256, 320, (float)CNT3, g3, be3, d_scale3, d_shift3);
}

// grid 4 x 1024: final BN over 1280 parts of 128 channels
__global__ void __launch_bounds__(1024) k_finS(const float* __restrict__ gs, const float* __restrict__ bes) {
    fin_block(blockIdx.x*32, d_pSs, d_pSq, 128, 1280, (float)R2, gs, bes, d_scaleS, d_shiftS);
}

// ---------------- three-body pass 2: warp-per-row, float4, reads precomputed W ----------------
__global__ void __launch_bounds__(256) k_pass2(const int* __restrict__ nbr_idx) {
    __shared__ float sS[8][128];
    __shared__ float sQ[8][128];
    int wid = threadIdx.x >> 5, lane = threadIdx.x & 31;
    int r = blockIdx.x*8 + wid;
    int n = r % NBR;
    int ba = r / NBR;
    int b = ba >> 7;
    int j = nbr_idx[r];
    int bj = b*AT + j;
    int jrow = bj*NBR;
    int offW = 0;
    if (lane < NK) {
        int m = lane + (lane >= n);
        offW = (jrow + m)*128;
    }
    const float4* PNa = (const float4*)(d_PN + ba*768);
    const float4* PNj = (const float4*)(d_PN + bj*768);
    const float4* QEr = (const float4*)(d_QE + r*512);
    float4 sg = ((const float4*)d_scale3)[lane];
    float4 hg = ((const float4*)d_shift3)[lane];
    float4 se = ((const float4*)d_scale3)[32 + lane];
    float4 he = ((const float4*)d_shift3)[32 + lane];
    float4 pag = PNa[lane],      pjg = PNj[64 + lane], qeg = QEr[lane];
    float4 pae = PNa[32 + lane], pje = PNj[96 + lane], qee = QEr[32 + lane];
    float4 baseg, basee;
    baseg.x = fmaf(sg.x, pag.x + pjg.x + qeg.x, hg.x);
    baseg.y = fmaf(sg.y, pag.y + pjg.y + qeg.y, hg.y);
    baseg.z = fmaf(sg.z, pag.z + pjg.z + qeg.z, hg.z);
    baseg.w = fmaf(sg.w, pag.w + pjg.w + qeg.w, hg.w);
    basee.x = fmaf(se.x, pae.x + pje.x + qee.x, he.x);
    basee.y = fmaf(se.y, pae.y + pje.y + qee.y, he.y);
    basee.z = fmaf(se.z, pae.z + pje.z + qee.z, he.z);
    basee.w = fmaf(se.w, pae.w + pje.w + qee.w, he.w);

    float4 acc = make_float4(0.f, 0.f, 0.f, 0.f);
    #pragma unroll
    for (int k = 0; k < NK; k++) {
        int oW = __shfl_sync(0xffffffffu, offW, k);
        float4 wg = *(const float4*)(d_Wg + oW + 4*lane);
        float4 we = *(const float4*)(d_We + oW + 4*lane);
        float gx = fmaf(sg.x, wg.x, baseg.x);
        float gy = fmaf(sg.y, wg.y, baseg.y);
        float gz = fmaf(sg.z, wg.z, baseg.z);
        float gw = fmaf(sg.w, wg.w, baseg.w);
        float ex = fmaf(se.x, we.x, basee.x);
        float ey = fmaf(se.y, we.y, basee.y);
        float ez = fmaf(se.z, we.z, basee.z);
        float ew = fmaf(se.w, we.w, basee.w);
        acc.x += sigmoid_hw(gx) * tanh_hw(ex);
        acc.y += sigmoid_hw(gy) * tanh_hw(ey);
        acc.z += sigmoid_hw(gz) * tanh_hw(ez);
        acc.w += sigmoid_hw(gw) * tanh_hw(ew);
    }
    ((float4*)(d_TB + r*128))[lane] = acc;
    ((float4*)sS[wid])[lane] = acc;
    float4 a2 = make_float4(acc.x*acc.x, acc.y*acc.y, acc.z*acc.z, acc.w*acc.w);
    ((float4*)sQ[wid])[lane] = a2;
    __syncthreads();
    if (threadIdx.x < 128) {
        float s = 0.f, q = 0.f;
        #pragma unroll
        for (int w = 0; w < 8; w++) { s += sS[w][threadIdx.x]; q += sQ[w][threadIdx.x]; }
        d_pSs[blockIdx.x*128 + threadIdx.x] = s;
        d_pSq[blockIdx.x*128 + threadIdx.x] = q;
    }
}

// ---------------- final: out = tanh(edge + two_body + BN(three_body)), float4 + HW tanh ----------------
__global__ void k_out(const float* __restrict__ edge, float* __restrict__ out) {
    int idx = blockIdx.x*256 + threadIdx.x;
    if (idx >= R2*32) return;
    int cl = idx & 31;
    int r = idx >> 5;
    float4 yg = ((const float4*)d_Y2)[r*64 + cl];
    float4 ye = ((const float4*)d_Y2)[r*64 + 32 + cl];
    float4 tb = ((const float4*)d_TB)[idx];
    float4 eg = ((const float4*)edge)[idx];
    float4 s2g = ((const float4*)d_scale2)[cl],      h2g = ((const float4*)d_shift2)[cl];
    float4 s2e = ((const float4*)d_scale2)[32 + cl], h2e = ((const float4*)d_shift2)[32 + cl];
    float4 sS4 = ((const float4*)d_scaleS)[cl],      hS4 = ((const float4*)d_shiftS)[cl];
    float4 o;
    o.x = tanh_hw(eg.x + sigmoid_hw(fmaf(s2g.x, yg.x, h2g.x))*tanh_hw(fmaf(s2e.x, ye.x, h2e.x)) + fmaf(sS4.x, tb.x, hS4.x));
    o.y = tanh_hw(eg.y + sigmoid_hw(fmaf(s2g.y, yg.y, h2g.y))*tanh_hw(fmaf(s2e.y, ye.y, h2e.y)) + fmaf(sS4.y, tb.y, hS4.y));
    o.z = tanh_hw(eg.z + sigmoid_hw(fmaf(s2g.z, yg.z, h2g.z))*tanh_hw(fmaf(s2e.z, ye.z, h2e.z)) + fmaf(sS4.z, tb.z, hS4.z));
    o.w = tanh_hw(eg.w + sigmoid_hw(fmaf(s2g.w, yg.w, h2g.w))*tanh_hw(fmaf(s2e.w, ye.w, h2e.w)) + fmaf(sS4.w, tb.w, hS4.w));
    ((float4*)out)[idx] = o;
}

// ---------------- launch ----------------
extern "C" void kernel_launch(void* const* d_in, const int* in_sizes, int n_in,
                              void* d_out, int out_size) {
    const float* node     = (const float*)d_in[0];
    const float* edge     = (const float*)d_in[1];
    const int*   nbr_idx  = (const int*)  d_in[2];
    const int*   nbr_mask = (const int*)  d_in[3];
    const float* W2       = (const float*)d_in[4];
    const float* W3       = (const float*)d_in[6];
    const float* g2  = (const float*)d_in[8];
    const float* be2 = (const float*)d_in[9];
    const float* g3  = (const float*)d_in[10];
    const float* be3 = (const float*)d_in[11];
    const float* gs  = (const float*)d_in[12];
    const float* bes = (const float*)d_in[13];
    float* out = (float*)d_out;

    // 1. all GEMMs (PN, QE, Y2 + fused BN2 stats), 3xTF32 k-chunk 32
    gemm_all<<<dim3(12, 168), 256>>>(node, edge, nbr_idx, nbr_mask, W2, W3);

    // 2. materialize w vectors + per-node aggregates S_j, Q_j
    k_prew<<<NODES, 256>>>(nbr_idx);

    // 3. three-body pass 1 (closed-form, warp-per-4-rows, 320 partials)
    k_pass1<<<320, 256>>>(nbr_idx);

    // 4. finalize BN2 + BN3
    k_fin23<<<16, 1024>>>(g2, be2, g3, be3);

    // 5. three-body pass 2 (warp-per-row float4, reads W; fused final-BN stats)
    k_pass2<<<1280, 256>>>(nbr_idx);

    // 6. finalize final BN
    k_finS<<<4, 1024>>>(gs, bes);

    // 7. output (HW tanh)
    k_out<<<1280, 256>>>(edge, out);
}